// round 2
// baseline (speedup 1.0000x reference)
#include <cuda_runtime.h>
#include <cstdint>
#include <math.h>

// Problem dims (fixed by the dataset)
#define T_STEPS 64
#define BATCH   64
#define HID     1024
#define EMB     1024
#define VOC     32000
#define NL      2
#define M2      (NL*BATCH)        // 128 stacked state rows
#define TB      (T_STEPS*BATCH)   // 4096

typedef unsigned long long ull;

// ---------------- device scratch (no cudaMalloc allowed) ----------------
__device__ float g_xpre[(size_t)TB * 3 * HID];   // [t*B+b][r|f|h] layer-0 input projections (+bias)
__device__ float g_h1hist[(size_t)TB * HID];     // h[1] per step, decoder input
__device__ float g_h[M2 * HID];                  // stacked state [l'*B+b][H]
__device__ float g_rh[M2 * HID];                 // r * h
__device__ float g_f[M2 * HID];                  // f gate
__device__ float g_xh[M2 * HID];                 // layer-1 x@Wh1 + bh1 staging
__device__ float g_WUr1[HID * HID];              // Wr[1] + Ur[1]
__device__ float g_WUf1[HID * HID];              // Wf[1] + Uf[1]

__device__ __forceinline__ float sigm(float x) { return 1.0f / (1.0f + expf(-x)); }

// -------- packed f32x2 primitives (Blackwell) --------
__device__ __forceinline__ ull pk2(float x) {
    ull r; asm("mov.b64 %0, {%1, %1};" : "=l"(r) : "f"(x)); return r;
}
__device__ __forceinline__ void fm2(ull& d, ull a, ull b) {
    asm("fma.rn.f32x2 %0, %1, %2, %3;" : "=l"(d) : "l"(a), "l"(b), "l"(d));
}
__device__ __forceinline__ float2 up2(ull v) {
    float2 f; asm("mov.b64 {%0, %1}, %2;" : "=f"(f.x), "=f"(f.y) : "l"(v)); return f;
}

// ---------------- f32x2 register-tiled GEMM core ----------------
// acc[TM/2][TN] accumulates C[m0+tm*TM + 2i+{0,1}][n0+tn*TN+j] for
// C = A @ W^T, A rows provided by arow(m) (length-K fp32, 16B aligned),
// Wb = &W[n0][0] row-major with row stride K.
// Smem layout: As: sm[0 .. 2*BK*BM), Ws: sm[2*BK*BM .. +2*BK*BN), k-major.
template<int BM, int BN, int BK, int TM, int TN, int NT, class AF>
__device__ __forceinline__ void gcore(AF arow, const float* __restrict__ Wb,
                                      int K, ull (&acc)[TM/2][TN],
                                      float* __restrict__ sm)
{
    const int tid = threadIdx.x;
    constexpr int KV  = BK / 4;
    constexpr int AIT = (BM * BK / 4) / NT;
    constexpr int WIT = (BN * BK / 4) / NT;
    static_assert(AIT * NT == BM * BK / 4, "A loader");
    static_assert(WIT * NT == BN * BK / 4, "W loader");

    float4 ar[AIT], wr[WIT];

    auto fetch = [&](int kt) {
        #pragma unroll
        for (int r = 0; r < AIT; r++) {
            int idx = r * NT + tid;
            int m = idx / KV, kk = (idx % KV) * 4;
            ar[r] = *(const float4*)(arow(m) + kt + kk);
        }
        #pragma unroll
        for (int r = 0; r < WIT; r++) {
            int idx = r * NT + tid;
            int n = idx / KV, kk = (idx % KV) * 4;
            wr[r] = *(const float4*)(Wb + (size_t)n * K + kt + kk);
        }
    };
    auto stos = [&](int buf) {
        float* As = sm + buf * BK * BM;
        float* Ws = sm + 2 * BK * BM + buf * BK * BN;
        #pragma unroll
        for (int r = 0; r < AIT; r++) {
            int idx = r * NT + tid;
            int m = idx / KV, kk = (idx % KV) * 4;
            As[(kk+0)*BM + m] = ar[r].x; As[(kk+1)*BM + m] = ar[r].y;
            As[(kk+2)*BM + m] = ar[r].z; As[(kk+3)*BM + m] = ar[r].w;
        }
        #pragma unroll
        for (int r = 0; r < WIT; r++) {
            int idx = r * NT + tid;
            int n = idx / KV, kk = (idx % KV) * 4;
            Ws[(kk+0)*BN + n] = wr[r].x; Ws[(kk+1)*BN + n] = wr[r].y;
            Ws[(kk+2)*BN + n] = wr[r].z; Ws[(kk+3)*BN + n] = wr[r].w;
        }
    };

    const int tn = tid % (BN / TN), tm = tid / (BN / TN);

    fetch(0);
    stos(0);
    __syncthreads();

    for (int kt = 0; kt < K; kt += BK) {
        const int buf = (kt / BK) & 1;
        if (kt + BK < K) fetch(kt + BK);

        const float* As = sm + buf * BK * BM + tm * TM;
        const float* Ws = sm + 2 * BK * BM + buf * BK * BN + tn * TN;
        #pragma unroll
        for (int k = 0; k < BK; k++) {
            ull a[TM/2];
            #pragma unroll
            for (int i = 0; i < TM/2; i += 2) {   // 16B LDS for row pairs
                ulonglong2 t = *(const ulonglong2*)(As + k * BM + 2 * i);
                a[i] = t.x; a[i+1] = t.y;
            }
            #pragma unroll
            for (int j = 0; j < TN; j++) {
                ull w = pk2(Ws[k * BN + j]);
                #pragma unroll
                for (int i = 0; i < TM/2; i++) fm2(acc[i][j], a[i], w);
            }
        }
        if (kt + BK < K) stos(buf ^ 1);
        __syncthreads();
    }
}

// ---------------- setup kernels ----------------
__global__ void k_hinit(const float* __restrict__ hidden) {
    int i = blockIdx.x * blockDim.x + threadIdx.x;
    if (i < M2 * HID) g_h[i] = hidden[i];
}

__global__ void k_hout(float* __restrict__ out) {
    int i = blockIdx.x * blockDim.x + threadIdx.x;
    if (i < M2 * HID) out[i] = g_h[i];
}

__global__ void k_addw(const float* __restrict__ Wr1, const float* __restrict__ Ur1,
                       const float* __restrict__ Wf1, const float* __restrict__ Uf1) {
    int i = blockIdx.x * blockDim.x + threadIdx.x;
    if (i < HID * HID) {
        g_WUr1[i] = Wr1[i] + Ur1[i];
        g_WUf1[i] = Wf1[i] + Uf1[i];
    }
}

// ---------------- precompute: xpre = gather(emb) @ [Wr0|Wf0|Wh0].T + bias ----------------
__global__ __launch_bounds__(256, 2)
void k_pre(const int* __restrict__ tokens, const float* __restrict__ emb,
           const float* __restrict__ W0, const float* __restrict__ W1, const float* __restrict__ W2,
           const float* __restrict__ b0, const float* __restrict__ b1, const float* __restrict__ b2)
{
    constexpr int BM = 128, BN = 128, BK = 16, TM = 8, TN = 8, NT = 256;
    __shared__ __align__(16) float sm[2*BK*BM + 2*BK*BN];
    __shared__ int stok[BM];

    const int m0 = blockIdx.y * BM, n0 = blockIdx.x * BN;
    const int seg = n0 >> 10, nn0 = n0 & 1023;
    const float* W    = (seg == 0) ? W0 : (seg == 1) ? W1 : W2;
    const float* bias = (seg == 0) ? b0 : (seg == 1) ? b1 : b2;

    if (threadIdx.x < BM) stok[threadIdx.x] = tokens[m0 + threadIdx.x];
    __syncthreads();

    ull acc[TM/2][TN] = {};
    auto arow = [&](int m) { return emb + (size_t)stok[m] * EMB; };
    gcore<BM,BN,BK,TM,TN,NT>(arow, W + (size_t)nn0 * HID, HID, acc, sm);

    const int tn = threadIdx.x % (BN/TN), tm = threadIdx.x / (BN/TN);
    #pragma unroll
    for (int i = 0; i < TM/2; i++) {
        const int m = m0 + tm*TM + 2*i;
        #pragma unroll
        for (int j = 0; j < TN; j++) {
            const int n  = n0  + tn*TN + j;
            const int nn = nn0 + tn*TN + j;
            float2 v = up2(acc[i][j]);
            g_xpre[(size_t)m       * (3*HID) + n] = v.x + bias[nn];
            g_xpre[(size_t)(m + 1) * (3*HID) + n] = v.y + bias[nn];
        }
    }
}

// ---------------- per-step kernels (BM=64,BN=32,BK=32,TM=8,TN=1,NT=256) ----------------
#define STEP_CFG constexpr int BM = 64, BN = 32, BK = 32, TM = 8, TN = 1, NT = 256;
#define STEP_SM  __shared__ __align__(16) float sm[2*BK*BM + 2*BK*BN];

__global__ __launch_bounds__(256)
void k_gates0(int t, const float* __restrict__ Ur0, const float* __restrict__ Uf0,
              const float* __restrict__ bur0, const float* __restrict__ buf0)
{
    STEP_CFG STEP_SM
    const int m0 = blockIdx.y * BM, n0 = blockIdx.x * BN;
    const int seg = n0 >> 10, nn0 = n0 & 1023;
    const float* W    = seg ? Uf0 : Ur0;
    const float* bias = seg ? buf0 : bur0;

    ull acc[TM/2][TN] = {};
    auto arow = [&](int m) { return g_h + (size_t)(m0 + m) * HID; };
    gcore<BM,BN,BK,TM,TN,NT>(arow, W + (size_t)nn0 * HID, HID, acc, sm);

    const int lane = threadIdx.x & 31, w = threadIdx.x >> 5;
    const int n = n0 + lane, nn = nn0 + lane;
    const float bs = bias[nn];
    #pragma unroll
    for (int i = 0; i < TM/2; i++) {
        float2 v = up2(acc[i][0]);
        #pragma unroll
        for (int p = 0; p < 2; p++) {
            const int m = m0 + w*TM + 2*i + p;
            const int b = m & (BATCH - 1);
            const float xadd = g_xpre[((size_t)t * BATCH + b) * (3*HID) + n];
            const float g = sigm((p ? v.y : v.x) + bs + xadd);
            const int idx = m * HID + nn;
            if (seg == 0) g_rh[idx] = g * g_h[idx];
            else          g_f[idx] = g;
        }
    }
}

__global__ __launch_bounds__(256)
void k_hwup0(int t, const float* __restrict__ Uh0, const float* __restrict__ buh0)
{
    STEP_CFG STEP_SM
    const int m0 = blockIdx.y * BM, n0 = blockIdx.x * BN;

    ull acc[TM/2][TN] = {};
    auto arow = [&](int m) { return g_rh + (size_t)(m0 + m) * HID; };
    gcore<BM,BN,BK,TM,TN,NT>(arow, Uh0 + (size_t)n0 * HID, HID, acc, sm);

    const int lane = threadIdx.x & 31, w = threadIdx.x >> 5;
    const int n = n0 + lane;
    const float bs = buh0[n];
    #pragma unroll
    for (int i = 0; i < TM/2; i++) {
        float2 v = up2(acc[i][0]);
        #pragma unroll
        for (int p = 0; p < 2; p++) {
            const int m = m0 + w*TM + 2*i + p;
            const int b = m & (BATCH - 1);
            const float xadd = g_xpre[((size_t)t * BATCH + b) * (3*HID) + 2*HID + n];
            const float hw = tanhf((p ? v.y : v.x) + bs + xadd);
            const int idx = m * HID + n;
            const float f = g_f[idx], h = g_h[idx];
            g_h[idx] = h + f * (hw - h);
        }
    }
}

__global__ __launch_bounds__(256)
void k_gates1(const float* __restrict__ Wh1,
              const float* __restrict__ br1, const float* __restrict__ bur1,
              const float* __restrict__ bf1, const float* __restrict__ buf1,
              const float* __restrict__ bh1)
{
    STEP_CFG STEP_SM
    const int m0 = blockIdx.y * BM, n0 = blockIdx.x * BN;
    const int seg = n0 >> 10, nn0 = n0 & 1023;
    const float* W = (seg == 0) ? g_WUr1 : (seg == 1) ? g_WUf1 : Wh1;

    ull acc[TM/2][TN] = {};
    auto arow = [&](int m) { return g_h + (size_t)(m0 + m) * HID; };
    gcore<BM,BN,BK,TM,TN,NT>(arow, W + (size_t)nn0 * HID, HID, acc, sm);

    const int lane = threadIdx.x & 31, w = threadIdx.x >> 5;
    const int nn = nn0 + lane;
    #pragma unroll
    for (int i = 0; i < TM/2; i++) {
        float2 v = up2(acc[i][0]);
        #pragma unroll
        for (int p = 0; p < 2; p++) {
            const int m = m0 + w*TM + 2*i + p;
            const int idx = m * HID + nn;
            const float a = p ? v.y : v.x;
            if (seg == 0) {
                const float r = sigm(a + br1[nn] + bur1[nn]);
                g_rh[idx] = r * g_h[idx];
            } else if (seg == 1) {
                g_f[idx] = sigm(a + bf1[nn] + buf1[nn]);
            } else {
                g_xh[idx] = a + bh1[nn];
            }
        }
    }
}

__global__ __launch_bounds__(256)
void k_hwup1(int t, const float* __restrict__ Uh1, const float* __restrict__ buh1)
{
    STEP_CFG STEP_SM
    const int m0 = blockIdx.y * BM, n0 = blockIdx.x * BN;

    ull acc[TM/2][TN] = {};
    auto arow = [&](int m) { return g_rh + (size_t)(m0 + m) * HID; };
    gcore<BM,BN,BK,TM,TN,NT>(arow, Uh1 + (size_t)n0 * HID, HID, acc, sm);

    const int lane = threadIdx.x & 31, w = threadIdx.x >> 5;
    const int n = n0 + lane;
    const float bs = buh1[n];
    #pragma unroll
    for (int i = 0; i < TM/2; i++) {
        float2 v = up2(acc[i][0]);
        #pragma unroll
        for (int p = 0; p < 2; p++) {
            const int m = m0 + w*TM + 2*i + p;
            const float hw = tanhf((p ? v.y : v.x) + bs + g_xh[m*HID + n]);
            const int idx = m * HID + n;
            const float f = g_f[idx], h = g_h[idx];
            const float nh = h + f * (hw - h);
            g_h[idx] = nh;
            if (m >= BATCH)
                g_h1hist[((size_t)t * BATCH + (m - BATCH)) * HID + n] = nh;
        }
    }
}

// ---------------- decoder: logits = h1hist @ Wdec.T + bdec ----------------
__global__ __launch_bounds__(256, 2)
void k_dec(const float* __restrict__ Wdec, const float* __restrict__ bdec,
           float* __restrict__ out)
{
    constexpr int BM = 128, BN = 128, BK = 16, TM = 8, TN = 8, NT = 256;
    __shared__ __align__(16) float sm[2*BK*BM + 2*BK*BN];
    const int m0 = blockIdx.y * BM, n0 = blockIdx.x * BN;

    ull acc[TM/2][TN] = {};
    auto arow = [&](int m) { return g_h1hist + (size_t)(m0 + m) * HID; };
    gcore<BM,BN,BK,TM,TN,NT>(arow, Wdec + (size_t)n0 * HID, HID, acc, sm);

    const int tn = threadIdx.x % (BN/TN), tm = threadIdx.x / (BN/TN);
    #pragma unroll
    for (int i = 0; i < TM/2; i++) {
        const int m = m0 + tm*TM + 2*i;
        #pragma unroll
        for (int j = 0; j < TN; j++) {
            const int n = n0 + tn*TN + j;
            float2 v = up2(acc[i][j]);
            out[(size_t)m       * VOC + n] = v.x + bdec[n];
            out[(size_t)(m + 1) * VOC + n] = v.y + bdec[n];
        }
    }
}

// ---------------- launch ----------------
extern "C" void kernel_launch(void* const* d_in, const int* in_sizes, int n_in,
                              void* d_out, int out_size)
{
    const int*   tokens = (const int*)  d_in[0];
    const float* hidden = (const float*)d_in[1];
    const float* emb    = (const float*)d_in[2];
    const float* Wr     = (const float*)d_in[3];
    const float* br     = (const float*)d_in[4];
    const float* Wf     = (const float*)d_in[5];
    const float* bf     = (const float*)d_in[6];
    const float* Wh     = (const float*)d_in[7];
    const float* bh     = (const float*)d_in[8];
    const float* Ur     = (const float*)d_in[9];
    const float* bur    = (const float*)d_in[10];
    const float* Ufw    = (const float*)d_in[11];
    const float* bufw   = (const float*)d_in[12];
    const float* Uh     = (const float*)d_in[13];
    const float* buh    = (const float*)d_in[14];
    const float* Wdec   = (const float*)d_in[15];
    const float* bdec   = (const float*)d_in[16];
    float* out = (float*)d_out;

    const size_t HH = (size_t)HID * HID;

    k_hinit<<<(M2*HID + 1023) / 1024, 1024>>>(hidden);
    k_addw<<<(HID*HID + 255) / 256, 256>>>(Wr + HH, Ur + HH, Wf + HH, Ufw + HH);
    k_pre<<<dim3(3*HID/128, TB/128), 256>>>(tokens, emb, Wr, Wf, Wh, br, bf, bh);

    for (int t = 0; t < T_STEPS; t++) {
        k_gates0<<<dim3(2*HID/32, M2/64), 256>>>(t, Ur, Ufw, bur, bufw);
        k_hwup0 <<<dim3(HID/32,   M2/64), 256>>>(t, Uh, buh);
        k_gates1<<<dim3(3*HID/32, M2/64), 256>>>(Wh + HH, br + HID, bur + HID,
                                                 bf + HID, bufw + HID, bh + HID);
        k_hwup1 <<<dim3(HID/32,   M2/64), 256>>>(t, Uh + HH, buh + HID);
    }

    k_dec<<<dim3(VOC/128, TB/128), 256>>>(Wdec, bdec, out);

    const long long logits_elems = (long long)TB * VOC;
    if ((long long)out_size >= logits_elems + (long long)M2 * HID)
        k_hout<<<(M2*HID + 1023) / 1024, 1024>>>(out + logits_elems);
}